// round 14
// baseline (speedup 1.0000x reference)
#include <cuda_runtime.h>
#include <cuda_bf16.h>
#include <cstdint>

#define T_STEPS 512
#define NN 32
#define DD 300
#define RR 3
#define EE 64
#define VGN 40000
#define KFLAT 9600   // NN*DD
#define TD (T_STEPS * DD)

#define KP 320       // padded K for logits GEMM (and recur k pad)
#define VP 40192     // padded V rows (157 x 256)
#define NP 384       // padded d for U/P tensor GEMMs (3 x 128)
#define KY 1280      // padded K for P GEMM (4 x 320)
#define UKS 30       // U k-splits (9600 / 320)
#define PKS 4        // P k-splits (1280 / 320)

// ---------------- scratch (device globals; no allocs allowed) ----------------
__device__ __nv_bfloat16 g_Xb[(size_t)T_STEPS * KFLAT]; // gathered x bf16
__device__ __nv_bfloat16 g_Wub[(size_t)NP * KFLAT];     // Wu^T bf16 [d][k]
__device__ __nv_bfloat16 g_Yb[(size_t)T_STEPS * KY];    // aggregated rows bf16
__device__ __nv_bfloat16 g_Wcatb[(size_t)NP * KY];      // [W0;convW]^T bf16
__device__ float g_UPp[(size_t)UKS * T_STEPS * NP];     // U split-k partials
__device__ float g_PPp[(size_t)PKS * T_STEPS * NP];     // P split-k partials
__device__ float g_U[(size_t)TD];                       // u_t
__device__ float g_P0[(size_t)TD];                      // proposed row 0 per t
__device__ __nv_bfloat16 g_Hb[(size_t)T_STEPS * KP];    // relu(mem0) bf16 padded
__device__ __nv_bfloat16 g_Wgb[(size_t)VP * KP];        // Wg bf16 padded

// ---------------- helpers ----------------
__device__ __forceinline__ unsigned long long pk64(unsigned a, unsigned b) {
    unsigned long long r;
    asm("mov.b64 %0, {%1, %2};" : "=l"(r) : "r"(a), "r"(b));
    return r;
}
__device__ __forceinline__ uint32_t smem_u32(const void* p) {
    uint32_t a;
    asm("{ .reg .u64 t; cvta.to.shared.u64 t, %1; cvt.u32.u64 %0, t; }" : "=r"(a) : "l"(p));
    return a;
}
__device__ __forceinline__ unsigned bf2pk(float a, float b) {
    return (unsigned)__bfloat16_as_ushort(__float2bfloat16(a)) |
           ((unsigned)__bfloat16_as_ushort(__float2bfloat16(b)) << 16);
}
__device__ __forceinline__ void fma2(unsigned long long& acc,
                                     unsigned long long a,
                                     unsigned long long b) {
    asm("fma.rn.f32x2 %0, %1, %2, %0;" : "+l"(acc) : "l"(a), "l"(b));
}
__device__ __forceinline__ void cpa16(uint32_t dst, const void* src) {
    unsigned long long g = (unsigned long long)__cvta_generic_to_global(src);
    asm volatile("cp.async.cg.shared.global [%0], [%1], 16;" :: "r"(dst), "l"(g) : "memory");
}

// ---------------- kernel 1: fused gather + coefY (per-t, x staged in smem) ---
__global__ __launch_bounds__(256) void k_gatherY(const int* __restrict__ xidx,
                                                 const float* __restrict__ X,
                                                 const int* __restrict__ esrc,
                                                 const int* __restrict__ edst) {
    int t = blockIdx.x;
    int tid = threadIdx.x;
    __shared__ int ids[NN];
    __shared__ __nv_bfloat16 xs[KFLAT];
    __shared__ int cnt[RR][NN];
    __shared__ float dinv[RR][NN];
    __shared__ float cval[RR][NN + 1];
    __shared__ int cidx[RR][NN + 1];
    __shared__ int cn[RR];

    if (tid < NN) ids[tid] = xidx[t * NN + tid];
    if (tid < RR * NN) cnt[tid / NN][tid % NN] = 0;
    __syncthreads();

    // gather + convert: write smem AND gmem
    for (int i = tid; i < KFLAT / 2; i += 256) {
        int e = 2 * i;
        int n = e / DD, k = e - n * DD;     // DD even -> pair stays in row
        const float* xr = X + (size_t)ids[n] * DD;
        unsigned p = bf2pk(xr[k], xr[k + 1]);
        *(unsigned*)&xs[e] = p;
        *(unsigned*)&g_Xb[(size_t)t * KFLAT + e] = p;
    }

    const int* es = esrc + (size_t)t * RR * EE;
    const int* ed = edst + (size_t)t * RR * EE;
    for (int j = tid; j < RR * EE; j += 256)
        atomicAdd(&cnt[j / EE][ed[j]], 1);   // integer atomics: deterministic
    __syncthreads();

    if (tid < RR * NN) {
        int r = tid / NN, n = tid % NN;
        dinv[r][n] = rsqrtf((float)(cnt[r][n] + 1));
    }
    __syncthreads();

    if (tid < RR) {
        int r = tid;
        float c[NN];
#pragma unroll
        for (int n = 0; n < NN; n++) c[n] = 0.f;
        for (int e = 0; e < EE; e++) {
            if (ed[r * EE + e] == 0) {
                int s = es[r * EE + e];
                c[s] += dinv[r][s];
            }
        }
        float d0 = dinv[r][0];
        c[0] += d0;               // self loop
        int m = 0;
        for (int n = 0; n < NN; n++) {
            if (c[n] != 0.f) { cidx[r][m] = n; cval[r][m] = c[n] * d0; m++; }
        }
        cn[r] = m;
    }
    __syncthreads();

    __nv_bfloat16* Yt = g_Yb + (size_t)t * KY;
    for (int k = tid; k < DD; k += 256) {
        Yt[k] = xs[k];   // s=0: x0
#pragma unroll
        for (int r = 0; r < RR; r++) {
            float a = 0.f;
            int m = cn[r];
            for (int q = 0; q < m; q++)
                a += cval[r][q] * __bfloat162float(xs[cidx[r][q] * DD + k]);
            Yt[(r + 1) * DD + k] = __float2bfloat16(a);
        }
    }
    if (tid < KY - 4 * DD)  // zero pad [1200, 1280)
        Yt[4 * DD + tid] = __float2bfloat16(0.f);
}

// ---------------- kernel 1b: Wg -> bf16 padded [VP][KP] + H pad cols ---------
__global__ void k_cvtW(const float* __restrict__ Wg) {
    size_t gidx = (size_t)blockIdx.x * blockDim.x + threadIdx.x;
    size_t i = gidx * 2;
    if (i < (size_t)VP * KP) {
        int v = (int)(i / KP), k = (int)(i - (size_t)v * KP);
        float a = (v < VGN && k < DD) ? Wg[(size_t)v * DD + k] : 0.f;
        float b = (v < VGN && k + 1 < DD) ? Wg[(size_t)v * DD + k + 1] : 0.f;
        *(unsigned*)&g_Wgb[i] = bf2pk(a, b);
    }
    if (gidx < T_STEPS * 20) {   // H pad cols [300,320)
        int t = (int)(gidx / 20), k = 300 + (int)(gidx - (gidx / 20) * 20);
        g_Hb[(size_t)t * KP + k] = __float2bfloat16(0.f);
    }
}

// ---------------- kernel 1d: Wu[k][d] -> Wub[d][k] bf16, d padded to NP ------
__global__ __launch_bounds__(1024) void k_trWu(const float* __restrict__ Wu) {
    __shared__ float smt[32][33];
    int k0 = blockIdx.x * 32, d0 = blockIdx.y * 32;
    int tx = threadIdx.x & 31, ty = threadIdx.x >> 5;
    int d = d0 + tx, k = k0 + ty;
    smt[ty][tx] = (d < DD) ? Wu[(size_t)k * DD + d] : 0.f;
    __syncthreads();
    g_Wub[(size_t)(d0 + ty) * KFLAT + k0 + tx] = __float2bfloat16(smt[tx][ty]);
}

// ---------------- kernel 1e: [W0;convW][k][d] -> Wcatb[d][k] bf16 ------------
__global__ __launch_bounds__(1024) void k_trWcat(const float* __restrict__ convW,
                                                 const float* __restrict__ W0) {
    __shared__ float smt[32][33];
    int k0 = blockIdx.x * 32, d0 = blockIdx.y * 32;
    int tx = threadIdx.x & 31, ty = threadIdx.x >> 5;
    int d = d0 + tx, k = k0 + ty;
    float v = 0.f;
    if (d < DD && k < 4 * DD) {
        int s = k / DD, kk = k - s * DD;
        const float* W = (s == 0) ? W0 : (convW + (size_t)(s - 1) * DD * DD);
        v = W[(size_t)kk * DD + d];
    }
    smt[ty][tx] = v;
    __syncthreads();
    g_Wcatb[(size_t)(d0 + ty) * KY + k0 + tx] = __float2bfloat16(smt[tx][ty]);
}

// ---------------- shared mma tile machinery ----------------
#define LPITCH 40

__device__ __forceinline__ void ldm_x4(uint32_t* f, uint32_t addr) {
    asm volatile("ldmatrix.sync.aligned.m8n8.x4.shared.b16 {%0,%1,%2,%3}, [%4];"
                 : "=r"(f[0]), "=r"(f[1]), "=r"(f[2]), "=r"(f[3]) : "r"(addr));
}
__device__ __forceinline__ void mma_bf16(float* c, const uint32_t* a,
                                         uint32_t b0, uint32_t b1) {
    asm volatile(
        "mma.sync.aligned.m16n8k16.row.col.f32.bf16.bf16.f32 "
        "{%0,%1,%2,%3}, {%4,%5,%6,%7}, {%8,%9}, {%0,%1,%2,%3};"
        : "+f"(c[0]), "+f"(c[1]), "+f"(c[2]), "+f"(c[3])
        : "r"(a[0]), "r"(a[1]), "r"(a[2]), "r"(a[3]), "r"(b0), "r"(b1));
}

// ---------------- kernel 2: split-K bf16 tensor GEMM (U and P paths) ---------
__global__ __launch_bounds__(256) void k_tcgemm(int mode) {
    const __nv_bfloat16* A = mode ? g_Yb : g_Xb;
    const __nv_bfloat16* B = mode ? g_Wcatb : g_Wub;
    float* outp = mode ? g_PPp : g_UPp;
    int kstr = mode ? KY : KFLAT;

    __shared__ __align__(16) __nv_bfloat16 As[128 * LPITCH];
    __shared__ __align__(16) __nv_bfloat16 Bs[128 * LPITCH];
    int tid = threadIdx.x;
    int wid = tid >> 5, lane = tid & 31;
    int wm = wid & 1, wn = wid >> 1;
    int v0 = blockIdx.x * 128;
    int t0 = blockIdx.y * 128;
    int kb0 = blockIdx.z * 320;

    float acc[4][4][4];
#pragma unroll
    for (int mt = 0; mt < 4; mt++)
#pragma unroll
        for (int nt = 0; nt < 4; nt++)
#pragma unroll
            for (int r = 0; r < 4; r++) acc[mt][nt][r] = 0.f;

    uint32_t sA = smem_u32(As), sB = smem_u32(Bs);
    int lrow = lane & 15;
    int lcol = (lane >> 4) << 3;

    for (int kb = 0; kb < 320; kb += 32) {
        __syncthreads();
#pragma unroll
        for (int h = 0; h < 2; h++) {
            int c = tid + h * 256;
            int r = c >> 2, q = c & 3;
            *(uint4*)(As + r * LPITCH + q * 8) =
                *(const uint4*)&A[(size_t)(t0 + r) * kstr + kb0 + kb + q * 8];
            *(uint4*)(Bs + r * LPITCH + q * 8) =
                *(const uint4*)&B[(size_t)(v0 + r) * kstr + kb0 + kb + q * 8];
        }
        __syncthreads();
#pragma unroll
        for (int ks = 0; ks < 32; ks += 16) {
            uint32_t af[4][4], bfr[2][4];
#pragma unroll
            for (int mt = 0; mt < 4; mt++)
                ldm_x4(af[mt],
                       sA + (uint32_t)(((wm * 64 + mt * 16 + lrow) * LPITCH + ks + lcol) * 2));
#pragma unroll
            for (int np = 0; np < 2; np++)
                ldm_x4(bfr[np],
                       sB + (uint32_t)(((wn * 32 + np * 16 + lrow) * LPITCH + ks + lcol) * 2));
#pragma unroll
            for (int mt = 0; mt < 4; mt++) {
#pragma unroll
                for (int nt = 0; nt < 4; nt++) {
                    int np = nt >> 1, sub = nt & 1;
                    mma_bf16(acc[mt][nt], af[mt], bfr[np][sub], bfr[np][sub + 2]);
                }
            }
        }
    }

    float* outz = outp + (size_t)blockIdx.z * T_STEPS * NP;
    int grp = lane >> 2, qc = (lane & 3) * 2;
#pragma unroll
    for (int nt = 0; nt < 4; nt++) {
        int v = v0 + wn * 32 + nt * 8 + qc;
#pragma unroll
        for (int mt = 0; mt < 4; mt++) {
            int t = t0 + wm * 64 + mt * 16 + grp;
            *(float2*)&outz[(size_t)t * NP + v] =
                make_float2(acc[mt][nt][0], acc[mt][nt][1]);
            *(float2*)&outz[(size_t)(t + 8) * NP + v] =
                make_float2(acc[mt][nt][2], acc[mt][nt][3]);
        }
    }
}

// ---------------- kernel 3c: reduce U (30) and P0 (4) partials ----------------
__global__ void k_reduce2() {
    int i = blockIdx.x * blockDim.x + threadIdx.x;
    if (i < TD) {
        int t = i / DD, d = i - (i / DD) * DD;
        float s = 0.f;
#pragma unroll
        for (int p = 0; p < UKS; p++) s += g_UPp[((size_t)p * T_STEPS + t) * NP + d];
        g_U[i] = s;
        float q = 0.f;
#pragma unroll
        for (int p = 0; p < PKS; p++) q += g_PPp[((size_t)p * T_STEPS + t) * NP + d];
        g_P0[i] = q;
    }
}

// ---------------- kernel 4: recurrence, 8-CTA cluster, TAG-POLLING sync ------
#define R8T 320
#define DBLK 40

__global__ void __launch_bounds__(R8T, 1) __cluster_dims__(8, 1, 1)
k_recur8(const float* __restrict__ Uu) {
    __shared__ uint2 mtag[2][KP];       // [buf][k] = {m_bits, tag}
    __shared__ float vpf[32][DBLK];     // partial v per k-chunk
    int tid = threadIdx.x;
    unsigned cta;
    asm("mov.u32 %0, %%cluster_ctarank;" : "=r"(cta));

    int kc = tid / 10;            // 0..31
    int dq = tid - kc * 10;       // 0..9
    int k0 = kc * 10;
    int dg = (int)cta * DBLK + dq * 4;   // multiple of 4 -> aligned float4
    bool act = dg < DD;
    bool pollable = (k0 < DD);           // chunks 30,31 are pad-only: never poll
    int dl4 = dq * 4;

    unsigned long long wlo[10], whi[10];
#pragma unroll
    for (int j = 0; j < 10; j++) { wlo[j] = 0ULL; whi[j] = 0ULL; }
    if (act && pollable) {
#pragma unroll
        for (int j = 0; j < 10; j++) {
            int k = k0 + j;
            if (k < DD) {
                float4 w = *(const float4*)&Uu[(size_t)k * DD + dg];
                wlo[j] = pk64(__float_as_uint(w.x), __float_as_uint(w.y));
                whi[j] = pk64(__float_as_uint(w.z), __float_as_uint(w.w));
            }
        }
    }

    for (int i = tid; i < KP; i += R8T) {
        mtag[0][i] = make_uint2(0u, 0u);
        mtag[1][i] = make_uint2(0u, 0xFFFFFFFFu);
    }
    __syncthreads();
    asm volatile("barrier.cluster.arrive.aligned;" ::: "memory");
    asm volatile("barrier.cluster.wait.aligned;" ::: "memory");

    int gi = tid;
    int gd = (int)cta * DBLK + gi;
    bool gact = (gi < DBLK) && (gd < DD);
    uint32_t mb0 = smem_u32(&mtag[0][0]);

    float un = 0.f, pn = 0.f, mprev = 0.f;
    if (gact) {
        un = g_U[gd];
        pn = g_P0[gd];
    }
    uint32_t paddr = mb0 + (uint32_t)(k0 * 8);

    for (int t = 0; t < T_STEPS; t++) {
        int par = t & 1;
        float uval = un, pval = pn;
        if (gact && t + 1 < T_STEPS) {
            un = g_U[(size_t)(t + 1) * DD + gd];
            pn = g_P0[(size_t)(t + 1) * DD + gd];
        }
        if (act) {
            uint32_t mv[10];
            if (pollable) {
                uint32_t base = paddr + (uint32_t)(par * KP * 8);
                unsigned want = (unsigned)t;
                while (true) {
                    unsigned ok = 1;
#pragma unroll
                    for (int j = 0; j < 10; j++) {
                        uint32_t mx, tg;
                        asm volatile("ld.volatile.shared.v2.u32 {%0, %1}, [%2];"
                                     : "=r"(mx), "=r"(tg) : "r"(base + (uint32_t)(j * 8)));
                        mv[j] = mx;
                        ok &= (tg == want) ? 1u : 0u;
                    }
                    if (ok) break;
                }
            } else {
#pragma unroll
                for (int j = 0; j < 10; j++) mv[j] = 0u;
            }
            unsigned long long acc0 = 0ULL, acc1 = 0ULL;
#pragma unroll
            for (int j = 0; j < 10; j++) {
                unsigned long long mm = pk64(mv[j], mv[j]);
                fma2(acc0, wlo[j], mm);
                fma2(acc1, whi[j], mm);
            }
            *(unsigned long long*)&vpf[kc][dl4] = acc0;
            *(unsigned long long*)&vpf[kc][dl4 + 2] = acc1;
        }
        __syncthreads();
        if (gact) {
            float vv[32];
#pragma unroll
            for (int c = 0; c < 32; c++) vv[c] = vpf[c][gi];
#pragma unroll
            for (int s = 1; s < 32; s <<= 1)
#pragma unroll
                for (int c = 0; c < 32; c += 2 * s) vv[c] = vv[c] + vv[c + s];
            float z = uval + vv[0];
            float g = 1.f / (1.f + __expf(-z));
            float mn = mprev + g * (pval - mprev);
            mprev = mn;
            g_Hb[(size_t)t * KP + gd] = __float2bfloat16(fmaxf(mn, 0.f));
            if (t + 1 < T_STEPS) {
                unsigned long long md = pk64(__float_as_uint(mn), (unsigned)(t + 1));
                uint32_t loff = mb0 + (uint32_t)(((par ^ 1) * KP + gd) * 8);
#pragma unroll
                for (unsigned r = 0; r < 8; r++) {
                    uint32_t ra;
                    asm("mapa.shared::cluster.u32 %0, %1, %2;" : "=r"(ra) : "r"(loff), "r"(r));
                    asm volatile("st.shared::cluster.b64 [%0], %1;" :: "r"(ra), "l"(md) : "memory");
                }
            }
        }
        __syncthreads();
    }
    asm volatile("barrier.cluster.arrive.aligned;" ::: "memory");
    asm volatile("barrier.cluster.wait.aligned;" ::: "memory");
}

// ---------------- kernel 5: logits mma.sync bf16, 128x256 tile, cp.async -----
__global__ void __launch_bounds__(256, 1) k_logits_mma(const float* __restrict__ bg,
                                                       float* __restrict__ out) {
    __shared__ __align__(16) __nv_bfloat16 As[2][128 * LPITCH];
    __shared__ __align__(16) __nv_bfloat16 Bs[2][256 * LPITCH];
    int tid = threadIdx.x;
    int wid = tid >> 5, lane = tid & 31;
    int wm = wid & 1, wn = wid >> 1;     // 2 m-halves x 4 n-quarters (64 v each)
    int v0 = blockIdx.x * 256;
    int t0 = blockIdx.y * 128;

    float acc[4][8][4];
#pragma unroll
    for (int mt = 0; mt < 4; mt++)
#pragma unroll
        for (int nt = 0; nt < 8; nt++)
#pragma unroll
            for (int r = 0; r < 4; r++) acc[mt][nt][r] = 0.f;

    uint32_t sA0 = smem_u32(As), sB0 = smem_u32(Bs);
    int lrow = lane & 15;
    int lcol = (lane >> 4) << 3;

    // loaders: 384 rows x 4 uint4 per stage = 1536 -> 6 per thread
    auto issue = [&](int i) {
        int kb = i * 32;
        uint32_t stA = sA0 + (uint32_t)(i & 1) * (128 * LPITCH * 2);
        uint32_t stB = sB0 + (uint32_t)(i & 1) * (256 * LPITCH * 2);
#pragma unroll
        for (int p = 0; p < 6; p++) {
            int c = tid + p * 256;
            int r = c >> 2, q = c & 3;
            uint32_t off = (uint32_t)((q * 8) * 2);
            if (r < 128) {
                cpa16(stA + (uint32_t)(r * LPITCH * 2) + off,
                      &g_Hb[(size_t)(t0 + r) * KP + kb + q * 8]);
            } else {
                int rb = r - 128;
                cpa16(stB + (uint32_t)(rb * LPITCH * 2) + off,
                      &g_Wgb[(size_t)(v0 + rb) * KP + kb + q * 8]);
            }
        }
        asm volatile("cp.async.commit_group;" ::: "memory");
    };

    issue(0);
    for (int i = 0; i < KP / 32; i++) {
        if (i + 1 < KP / 32) {
            issue(i + 1);
            asm volatile("cp.async.wait_group 1;" ::: "memory");
        } else {
            asm volatile("cp.async.wait_group 0;" ::: "memory");
        }
        __syncthreads();
        uint32_t sA = sA0 + (uint32_t)(i & 1) * (128 * LPITCH * 2);
        uint32_t sB = sB0 + (uint32_t)(i & 1) * (256 * LPITCH * 2);
#pragma unroll
        for (int ks = 0; ks < 32; ks += 16) {
            uint32_t af[4][4], bfr[4][4];
#pragma unroll
            for (int mt = 0; mt < 4; mt++)
                ldm_x4(af[mt],
                       sA + (uint32_t)(((wm * 64 + mt * 16 + lrow) * LPITCH + ks + lcol) * 2));
#pragma unroll
            for (int np = 0; np < 4; np++)
                ldm_x4(bfr[np],
                       sB + (uint32_t)(((wn * 64 + np * 16 + lrow) * LPITCH + ks + lcol) * 2));
#pragma unroll
            for (int mt = 0; mt < 4; mt++) {
#pragma unroll
                for (int nt = 0; nt < 8; nt++) {
                    int np = nt >> 1, sub = nt & 1;
                    mma_bf16(acc[mt][nt], af[mt], bfr[np][sub], bfr[np][sub + 2]);
                }
            }
        }
        __syncthreads();   // protect buffer (i&1) before stage i+2 overwrites
    }

    int grp = lane >> 2, qc = (lane & 3) * 2;
#pragma unroll
    for (int nt = 0; nt < 8; nt++) {
        int v = v0 + wn * 64 + nt * 8 + qc;
        if (v >= VGN) continue;
        float b0 = bg[v], b1 = bg[v + 1];
#pragma unroll
        for (int mt = 0; mt < 4; mt++) {
            int t = t0 + wm * 64 + mt * 16 + grp;
            float2 o0 = make_float2(acc[mt][nt][0] + b0, acc[mt][nt][1] + b1);
            float2 o1 = make_float2(acc[mt][nt][2] + b0, acc[mt][nt][3] + b1);
            *(float2*)&out[(size_t)t * VGN + v] = o0;
            *(float2*)&out[(size_t)(t + 8) * VGN + v] = o1;
        }
    }
}

// ---------------- kernel 6: log_softmax, online max+sum (2 passes total) -----
__global__ __launch_bounds__(512) void k_logsoftmax(float* __restrict__ out) {
    int t = blockIdx.x;
    float* row = out + (size_t)t * VGN;
    __shared__ float rm[16], rs[16];
    int tid = threadIdx.x;
    int lane = tid & 31, w = tid >> 5;

    float mr = -1e30f, sr = 0.f;
    const float4* row4 = (const float4*)row;
    for (int v = tid; v < VGN / 4; v += 512) {
        float4 x = row4[v];
        float xs[4] = {x.x, x.y, x.z, x.w};
#pragma unroll
        for (int c = 0; c < 4; c++) {
            float xv = xs[c];
            if (xv <= mr) {
                sr += __expf(xv - mr);
            } else {
                sr = sr * __expf(mr - xv) + 1.f;
                mr = xv;
            }
        }
    }
#pragma unroll
    for (int o = 16; o; o >>= 1) {
        float mo = __shfl_xor_sync(~0u, mr, o);
        float so = __shfl_xor_sync(~0u, sr, o);
        float nm = fmaxf(mr, mo);
        sr = sr * __expf(mr - nm) + so * __expf(mo - nm);
        mr = nm;
    }
    if (lane == 0) { rm[w] = mr; rs[w] = sr; }
    __syncthreads();
    if (tid == 0) {
        float M = rm[0], S = rs[0];
#pragma unroll
        for (int i = 1; i < 16; i++) {
            float nm = fmaxf(M, rm[i]);
            S = S * __expf(M - nm) + rs[i] * __expf(rm[i] - nm);
            M = nm;
        }
        rm[0] = M + logf(S);
    }
    __syncthreads();
    float lse = rm[0];

    float4* row4w = (float4*)row;
    for (int v = tid; v < VGN / 4; v += 512) {
        float4 x = row4w[v];
        x.x -= lse; x.y -= lse; x.z -= lse; x.w -= lse;
        row4w[v] = x;
    }
}

// ---------------- tail zero (second ref output = zeros) ----------------
__global__ void k_zero(float* out, size_t start, size_t n) {
    size_t i = (size_t)blockIdx.x * blockDim.x + threadIdx.x;
    if (i < n) out[start + i] = 0.f;
}

extern "C" void kernel_launch(void* const* d_in, const int* in_sizes, int n_in,
                              void* d_out, int out_size) {
    const int*   xidx  = (const int*)d_in[0];
    const int*   esrc  = (const int*)d_in[1];
    const int*   edst  = (const int*)d_in[2];
    const float* X     = (const float*)d_in[3];
    const float* convW = (const float*)d_in[4];
    const float* W0    = (const float*)d_in[5];
    const float* Wu    = (const float*)d_in[6];
    const float* Uu    = (const float*)d_in[7];
    const float* Wg    = (const float*)d_in[8];
    const float* bg    = (const float*)d_in[9];
    float* out = (float*)d_out;

    k_gatherY<<<T_STEPS, 256>>>(xidx, X, esrc, edst);
    {
        size_t nw = ((size_t)VP * KP) / 2;
        k_cvtW<<<(unsigned)((nw + 255) / 256), 256>>>(Wg);
    }
    k_trWu<<<dim3(KFLAT / 32, NP / 32), 1024>>>(Wu);
    k_trWcat<<<dim3(KY / 32, NP / 32), 1024>>>(convW, W0);
    k_tcgemm<<<dim3(3, 4, UKS), 256>>>(0);   // U partials
    k_tcgemm<<<dim3(3, 4, PKS), 256>>>(1);   // P partials
    k_reduce2<<<(TD + 255) / 256, 256>>>();
    k_recur8<<<8, R8T>>>(Uu);
    k_logits_mma<<<dim3(VP / 256, T_STEPS / 128), 256>>>(bg, out);
    k_logsoftmax<<<T_STEPS, 512>>>(out);

    size_t used = (size_t)T_STEPS * VGN;
    if ((size_t)out_size > used) {
        size_t n = (size_t)out_size - used;
        k_zero<<<(unsigned)((n + 255) / 256), 256>>>(out, used, n);
    }
}

// round 16
// speedup vs baseline: 1.0287x; 1.0287x over previous
#include <cuda_runtime.h>
#include <cuda_bf16.h>
#include <cstdint>

#define T_STEPS 512
#define NN 32
#define DD 300
#define RR 3
#define EE 64
#define VGN 40000
#define KFLAT 9600   // NN*DD
#define TD (T_STEPS * DD)

#define KP 320       // padded K for logits GEMM (and recur k pad)
#define VP 40064     // padded V rows (313 x 128)
#define NP 384       // padded d for U/P tensor GEMMs (3 x 128)
#define KY 1280      // padded K for P GEMM (4 x 320)
#define UKS 30       // U k-splits (9600 / 320)
#define PKS 4        // P k-splits (1280 / 320)

// ---------------- scratch (device globals; no allocs allowed) ----------------
__device__ __nv_bfloat16 g_Xb[(size_t)T_STEPS * KFLAT]; // gathered x bf16
__device__ __nv_bfloat16 g_Wub[(size_t)NP * KFLAT];     // Wu^T bf16 [d][k]
__device__ __nv_bfloat16 g_Yb[(size_t)T_STEPS * KY];    // aggregated rows bf16
__device__ __nv_bfloat16 g_Wcatb[(size_t)NP * KY];      // [W0;convW]^T bf16
__device__ float g_UPp[(size_t)UKS * T_STEPS * NP];     // U split-k partials
__device__ float g_PPp[(size_t)PKS * T_STEPS * NP];     // P split-k partials
__device__ float g_U[(size_t)TD];                       // u_t
__device__ float g_P0[(size_t)TD];                      // proposed row 0 per t
__device__ __nv_bfloat16 g_Hb[(size_t)T_STEPS * KP];    // relu(mem0) bf16 padded
__device__ __nv_bfloat16 g_Wgb[(size_t)VP * KP];        // Wg bf16 padded

// ---------------- helpers ----------------
__device__ __forceinline__ unsigned long long pk64(unsigned a, unsigned b) {
    unsigned long long r;
    asm("mov.b64 %0, {%1, %2};" : "=l"(r) : "r"(a), "r"(b));
    return r;
}
__device__ __forceinline__ uint32_t smem_u32(const void* p) {
    uint32_t a;
    asm("{ .reg .u64 t; cvta.to.shared.u64 t, %1; cvt.u32.u64 %0, t; }" : "=r"(a) : "l"(p));
    return a;
}
__device__ __forceinline__ unsigned bf2pk(float a, float b) {
    return (unsigned)__bfloat16_as_ushort(__float2bfloat16(a)) |
           ((unsigned)__bfloat16_as_ushort(__float2bfloat16(b)) << 16);
}
__device__ __forceinline__ void fma2(unsigned long long& acc,
                                     unsigned long long a,
                                     unsigned long long b) {
    asm("fma.rn.f32x2 %0, %1, %2, %0;" : "+l"(acc) : "l"(a), "l"(b));
}
__device__ __forceinline__ void cpa16(uint32_t dst, const void* src) {
    unsigned long long g = (unsigned long long)__cvta_generic_to_global(src);
    asm volatile("cp.async.cg.shared.global [%0], [%1], 16;" :: "r"(dst), "l"(g) : "memory");
}

// ---------------- kernel 1: fused gather + coefY (per-t, x staged in smem) ---
__global__ __launch_bounds__(256) void k_gatherY(const int* __restrict__ xidx,
                                                 const float* __restrict__ X,
                                                 const int* __restrict__ esrc,
                                                 const int* __restrict__ edst) {
    int t = blockIdx.x;
    int tid = threadIdx.x;
    __shared__ int ids[NN];
    __shared__ __nv_bfloat16 xs[KFLAT];
    __shared__ int cnt[RR][NN];
    __shared__ float dinv[RR][NN];
    __shared__ float cval[RR][NN + 1];
    __shared__ int cidx[RR][NN + 1];
    __shared__ int cn[RR];

    if (tid < NN) ids[tid] = xidx[t * NN + tid];
    if (tid < RR * NN) cnt[tid / NN][tid % NN] = 0;
    __syncthreads();

    for (int i = tid; i < KFLAT / 2; i += 256) {
        int e = 2 * i;
        int n = e / DD, k = e - n * DD;     // DD even -> pair stays in row
        const float* xr = X + (size_t)ids[n] * DD;
        unsigned p = bf2pk(xr[k], xr[k + 1]);
        *(unsigned*)&xs[e] = p;
        *(unsigned*)&g_Xb[(size_t)t * KFLAT + e] = p;
    }

    const int* es = esrc + (size_t)t * RR * EE;
    const int* ed = edst + (size_t)t * RR * EE;
    for (int j = tid; j < RR * EE; j += 256)
        atomicAdd(&cnt[j / EE][ed[j]], 1);   // integer atomics: deterministic
    __syncthreads();

    if (tid < RR * NN) {
        int r = tid / NN, n = tid % NN;
        dinv[r][n] = rsqrtf((float)(cnt[r][n] + 1));
    }
    __syncthreads();

    if (tid < RR) {
        int r = tid;
        float c[NN];
#pragma unroll
        for (int n = 0; n < NN; n++) c[n] = 0.f;
        for (int e = 0; e < EE; e++) {
            if (ed[r * EE + e] == 0) {
                int s = es[r * EE + e];
                c[s] += dinv[r][s];
            }
        }
        float d0 = dinv[r][0];
        c[0] += d0;               // self loop
        int m = 0;
        for (int n = 0; n < NN; n++) {
            if (c[n] != 0.f) { cidx[r][m] = n; cval[r][m] = c[n] * d0; m++; }
        }
        cn[r] = m;
    }
    __syncthreads();

    __nv_bfloat16* Yt = g_Yb + (size_t)t * KY;
    for (int k = tid; k < DD; k += 256) {
        Yt[k] = xs[k];   // s=0: x0
#pragma unroll
        for (int r = 0; r < RR; r++) {
            float a = 0.f;
            int m = cn[r];
            for (int q = 0; q < m; q++)
                a += cval[r][q] * __bfloat162float(xs[cidx[r][q] * DD + k]);
            Yt[(r + 1) * DD + k] = __float2bfloat16(a);
        }
    }
    if (tid < KY - 4 * DD)  // zero pad [1200, 1280)
        Yt[4 * DD + tid] = __float2bfloat16(0.f);
}

// ---------------- kernel 1b: Wg -> bf16 padded [VP][KP] + H pad cols ---------
__global__ void k_cvtW(const float* __restrict__ Wg) {
    size_t gidx = (size_t)blockIdx.x * blockDim.x + threadIdx.x;
    size_t i = gidx * 2;
    if (i < (size_t)VP * KP) {
        int v = (int)(i / KP), k = (int)(i - (size_t)v * KP);
        float a = (v < VGN && k < DD) ? Wg[(size_t)v * DD + k] : 0.f;
        float b = (v < VGN && k + 1 < DD) ? Wg[(size_t)v * DD + k + 1] : 0.f;
        *(unsigned*)&g_Wgb[i] = bf2pk(a, b);
    }
    if (gidx < T_STEPS * 20) {   // H pad cols [300,320)
        int t = (int)(gidx / 20), k = 300 + (int)(gidx - (gidx / 20) * 20);
        g_Hb[(size_t)t * KP + k] = __float2bfloat16(0.f);
    }
}

// ---------------- kernel 1d: Wu[k][d] -> Wub[d][k] bf16, d padded to NP ------
__global__ __launch_bounds__(1024) void k_trWu(const float* __restrict__ Wu) {
    __shared__ float smt[32][33];
    int k0 = blockIdx.x * 32, d0 = blockIdx.y * 32;
    int tx = threadIdx.x & 31, ty = threadIdx.x >> 5;
    int d = d0 + tx, k = k0 + ty;
    smt[ty][tx] = (d < DD) ? Wu[(size_t)k * DD + d] : 0.f;
    __syncthreads();
    g_Wub[(size_t)(d0 + ty) * KFLAT + k0 + tx] = __float2bfloat16(smt[tx][ty]);
}

// ---------------- kernel 1e: [W0;convW][k][d] -> Wcatb[d][k] bf16 ------------
__global__ __launch_bounds__(1024) void k_trWcat(const float* __restrict__ convW,
                                                 const float* __restrict__ W0) {
    __shared__ float smt[32][33];
    int k0 = blockIdx.x * 32, d0 = blockIdx.y * 32;
    int tx = threadIdx.x & 31, ty = threadIdx.x >> 5;
    int d = d0 + tx, k = k0 + ty;
    float v = 0.f;
    if (d < DD && k < 4 * DD) {
        int s = k / DD, kk = k - s * DD;
        const float* W = (s == 0) ? W0 : (convW + (size_t)(s - 1) * DD * DD);
        v = W[(size_t)kk * DD + d];
    }
    smt[ty][tx] = v;
    __syncthreads();
    g_Wcatb[(size_t)(d0 + ty) * KY + k0 + tx] = __float2bfloat16(smt[tx][ty]);
}

// ---------------- shared mma tile machinery ----------------
#define LPITCH 40

__device__ __forceinline__ void ldm_x4(uint32_t* f, uint32_t addr) {
    asm volatile("ldmatrix.sync.aligned.m8n8.x4.shared.b16 {%0,%1,%2,%3}, [%4];"
                 : "=r"(f[0]), "=r"(f[1]), "=r"(f[2]), "=r"(f[3]) : "r"(addr));
}
__device__ __forceinline__ void mma_bf16(float* c, const uint32_t* a,
                                         uint32_t b0, uint32_t b1) {
    asm volatile(
        "mma.sync.aligned.m16n8k16.row.col.f32.bf16.bf16.f32 "
        "{%0,%1,%2,%3}, {%4,%5,%6,%7}, {%8,%9}, {%0,%1,%2,%3};"
        : "+f"(c[0]), "+f"(c[1]), "+f"(c[2]), "+f"(c[3])
        : "r"(a[0]), "r"(a[1]), "r"(a[2]), "r"(a[3]), "r"(b0), "r"(b1));
}

// ---------------- kernel 2: split-K bf16 tensor GEMM (U and P paths) ---------
__global__ __launch_bounds__(256) void k_tcgemm(int mode) {
    const __nv_bfloat16* A = mode ? g_Yb : g_Xb;
    const __nv_bfloat16* B = mode ? g_Wcatb : g_Wub;
    float* outp = mode ? g_PPp : g_UPp;
    int kstr = mode ? KY : KFLAT;

    __shared__ __align__(16) __nv_bfloat16 As[128 * LPITCH];
    __shared__ __align__(16) __nv_bfloat16 Bs[128 * LPITCH];
    int tid = threadIdx.x;
    int wid = tid >> 5, lane = tid & 31;
    int wm = wid & 1, wn = wid >> 1;
    int v0 = blockIdx.x * 128;
    int t0 = blockIdx.y * 128;
    int kb0 = blockIdx.z * 320;

    float acc[4][4][4];
#pragma unroll
    for (int mt = 0; mt < 4; mt++)
#pragma unroll
        for (int nt = 0; nt < 4; nt++)
#pragma unroll
            for (int r = 0; r < 4; r++) acc[mt][nt][r] = 0.f;

    uint32_t sA = smem_u32(As), sB = smem_u32(Bs);
    int lrow = lane & 15;
    int lcol = (lane >> 4) << 3;

    for (int kb = 0; kb < 320; kb += 32) {
        __syncthreads();
#pragma unroll
        for (int h = 0; h < 2; h++) {
            int c = tid + h * 256;
            int r = c >> 2, q = c & 3;
            *(uint4*)(As + r * LPITCH + q * 8) =
                *(const uint4*)&A[(size_t)(t0 + r) * kstr + kb0 + kb + q * 8];
            *(uint4*)(Bs + r * LPITCH + q * 8) =
                *(const uint4*)&B[(size_t)(v0 + r) * kstr + kb0 + kb + q * 8];
        }
        __syncthreads();
#pragma unroll
        for (int ks = 0; ks < 32; ks += 16) {
            uint32_t af[4][4], bfr[2][4];
#pragma unroll
            for (int mt = 0; mt < 4; mt++)
                ldm_x4(af[mt],
                       sA + (uint32_t)(((wm * 64 + mt * 16 + lrow) * LPITCH + ks + lcol) * 2));
#pragma unroll
            for (int np = 0; np < 2; np++)
                ldm_x4(bfr[np],
                       sB + (uint32_t)(((wn * 32 + np * 16 + lrow) * LPITCH + ks + lcol) * 2));
#pragma unroll
            for (int mt = 0; mt < 4; mt++) {
#pragma unroll
                for (int nt = 0; nt < 4; nt++) {
                    int np = nt >> 1, sub = nt & 1;
                    mma_bf16(acc[mt][nt], af[mt], bfr[np][sub], bfr[np][sub + 2]);
                }
            }
        }
    }

    float* outz = outp + (size_t)blockIdx.z * T_STEPS * NP;
    int grp = lane >> 2, qc = (lane & 3) * 2;
#pragma unroll
    for (int nt = 0; nt < 4; nt++) {
        int v = v0 + wn * 32 + nt * 8 + qc;
#pragma unroll
        for (int mt = 0; mt < 4; mt++) {
            int t = t0 + wm * 64 + mt * 16 + grp;
            *(float2*)&outz[(size_t)t * NP + v] =
                make_float2(acc[mt][nt][0], acc[mt][nt][1]);
            *(float2*)&outz[(size_t)(t + 8) * NP + v] =
                make_float2(acc[mt][nt][2], acc[mt][nt][3]);
        }
    }
}

// ---------------- kernel 3c: reduce U (30) and P0 (4) partials ----------------
__global__ void k_reduce2() {
    int i = blockIdx.x * blockDim.x + threadIdx.x;
    if (i < TD) {
        int t = i / DD, d = i - (i / DD) * DD;
        float s = 0.f;
#pragma unroll
        for (int p = 0; p < UKS; p++) s += g_UPp[((size_t)p * T_STEPS + t) * NP + d];
        g_U[i] = s;
        float q = 0.f;
#pragma unroll
        for (int p = 0; p < PKS; p++) q += g_PPp[((size_t)p * T_STEPS + t) * NP + d];
        g_P0[i] = q;
    }
}

// ---------------- kernel 4: recurrence, 8-CTA cluster, TAG-POLLING sync ------
#define R8T 320
#define DBLK 40

__global__ void __launch_bounds__(R8T, 1) __cluster_dims__(8, 1, 1)
k_recur8(const float* __restrict__ Uu) {
    __shared__ uint2 mtag[2][KP];       // [buf][k] = {m_bits, tag}
    __shared__ float vpf[32][DBLK];     // partial v per k-chunk
    int tid = threadIdx.x;
    unsigned cta;
    asm("mov.u32 %0, %%cluster_ctarank;" : "=r"(cta));

    int kc = tid / 10;            // 0..31
    int dq = tid - kc * 10;       // 0..9
    int k0 = kc * 10;
    int dg = (int)cta * DBLK + dq * 4;   // multiple of 4 -> aligned float4
    bool act = dg < DD;
    bool pollable = (k0 < DD);           // chunks 30,31 are pad-only: never poll
    int dl4 = dq * 4;

    unsigned long long wlo[10], whi[10];
#pragma unroll
    for (int j = 0; j < 10; j++) { wlo[j] = 0ULL; whi[j] = 0ULL; }
    if (act && pollable) {
#pragma unroll
        for (int j = 0; j < 10; j++) {
            int k = k0 + j;
            if (k < DD) {
                float4 w = *(const float4*)&Uu[(size_t)k * DD + dg];
                wlo[j] = pk64(__float_as_uint(w.x), __float_as_uint(w.y));
                whi[j] = pk64(__float_as_uint(w.z), __float_as_uint(w.w));
            }
        }
    }

    for (int i = tid; i < KP; i += R8T) {
        mtag[0][i] = make_uint2(0u, 0u);
        mtag[1][i] = make_uint2(0u, 0xFFFFFFFFu);
    }
    __syncthreads();
    asm volatile("barrier.cluster.arrive.aligned;" ::: "memory");
    asm volatile("barrier.cluster.wait.aligned;" ::: "memory");

    int gi = tid;
    int gd = (int)cta * DBLK + gi;
    bool gact = (gi < DBLK) && (gd < DD);
    uint32_t mb0 = smem_u32(&mtag[0][0]);

    float un = 0.f, pn = 0.f, mprev = 0.f;
    if (gact) {
        un = g_U[gd];
        pn = g_P0[gd];
    }
    uint32_t paddr = mb0 + (uint32_t)(k0 * 8);

    for (int t = 0; t < T_STEPS; t++) {
        int par = t & 1;
        float uval = un, pval = pn;
        if (gact && t + 1 < T_STEPS) {
            un = g_U[(size_t)(t + 1) * DD + gd];
            pn = g_P0[(size_t)(t + 1) * DD + gd];
        }
        if (act) {
            uint32_t mv[10];
            if (pollable) {
                uint32_t base = paddr + (uint32_t)(par * KP * 8);
                unsigned want = (unsigned)t;
                while (true) {
                    unsigned ok = 1;
#pragma unroll
                    for (int j = 0; j < 10; j++) {
                        uint32_t mx, tg;
                        asm volatile("ld.volatile.shared.v2.u32 {%0, %1}, [%2];"
                                     : "=r"(mx), "=r"(tg) : "r"(base + (uint32_t)(j * 8)));
                        mv[j] = mx;
                        ok &= (tg == want) ? 1u : 0u;
                    }
                    if (ok) break;
                }
            } else {
#pragma unroll
                for (int j = 0; j < 10; j++) mv[j] = 0u;
            }
            unsigned long long acc0 = 0ULL, acc1 = 0ULL;
#pragma unroll
            for (int j = 0; j < 10; j++) {
                unsigned long long mm = pk64(mv[j], mv[j]);
                fma2(acc0, wlo[j], mm);
                fma2(acc1, whi[j], mm);
            }
            *(unsigned long long*)&vpf[kc][dl4] = acc0;
            *(unsigned long long*)&vpf[kc][dl4 + 2] = acc1;
        }
        __syncthreads();
        if (gact) {
            float vv[32];
#pragma unroll
            for (int c = 0; c < 32; c++) vv[c] = vpf[c][gi];
#pragma unroll
            for (int s = 1; s < 32; s <<= 1)
#pragma unroll
                for (int c = 0; c < 32; c += 2 * s) vv[c] = vv[c] + vv[c + s];
            float z = uval + vv[0];
            float g = 1.f / (1.f + __expf(-z));
            float mn = mprev + g * (pval - mprev);
            mprev = mn;
            g_Hb[(size_t)t * KP + gd] = __float2bfloat16(fmaxf(mn, 0.f));
            if (t + 1 < T_STEPS) {
                unsigned long long md = pk64(__float_as_uint(mn), (unsigned)(t + 1));
                uint32_t loff = mb0 + (uint32_t)(((par ^ 1) * KP + gd) * 8);
#pragma unroll
                for (unsigned r = 0; r < 8; r++) {
                    uint32_t ra;
                    asm("mapa.shared::cluster.u32 %0, %1, %2;" : "=r"(ra) : "r"(loff), "r"(r));
                    asm volatile("st.shared::cluster.b64 [%0], %1;" :: "r"(ra), "l"(md) : "memory");
                }
            }
        }
        __syncthreads();
    }
    asm volatile("barrier.cluster.arrive.aligned;" ::: "memory");
    asm volatile("barrier.cluster.wait.aligned;" ::: "memory");
}

// ---------------- kernel 5: logits mma.sync bf16, 128x128 tile, 3-stage ------
// 3-buffer cp.async pipeline, ONE syncthreads per k-iteration: issue(i+2) at
// iter i overwrites buf (i-1)%3, which all threads finished reading before
// this iter's syncthreads.
__global__ __launch_bounds__(256) void k_logits_mma(const float* __restrict__ bg,
                                                    float* __restrict__ out) {
    __shared__ __align__(16) __nv_bfloat16 As[3][128 * LPITCH];
    __shared__ __align__(16) __nv_bfloat16 Bs[3][128 * LPITCH];
    int tid = threadIdx.x;
    int wid = tid >> 5, lane = tid & 31;
    int wm = wid & 1, wn = wid >> 1;
    int v0 = blockIdx.x * 128;
    int t0 = blockIdx.y * 128;

    float acc[4][4][4];
#pragma unroll
    for (int mt = 0; mt < 4; mt++)
#pragma unroll
        for (int nt = 0; nt < 4; nt++)
#pragma unroll
            for (int r = 0; r < 4; r++) acc[mt][nt][r] = 0.f;

    uint32_t sA0 = smem_u32(As), sB0 = smem_u32(Bs);
    int lrow = lane & 15;
    int lcol = (lane >> 4) << 3;
    int r_ld = tid >> 2, q_ld = tid & 3;      // 64 rows per pass, 2 passes

    auto issue = [&](int i) {
        int kb = i * 32;
        uint32_t st = (uint32_t)(i % 3) * (128 * LPITCH * 2);
#pragma unroll
        for (int h = 0; h < 2; h++) {
            int r = r_ld + h * 64;
            uint32_t off = st + (uint32_t)((r * LPITCH + q_ld * 8) * 2);
            cpa16(sA0 + off, &g_Hb[(size_t)(t0 + r) * KP + kb + q_ld * 8]);
            cpa16(sB0 + off, &g_Wgb[(size_t)(v0 + r) * KP + kb + q_ld * 8]);
        }
        asm volatile("cp.async.commit_group;" ::: "memory");
    };

    issue(0);
    issue(1);
    for (int i = 0; i < KP / 32; i++) {
        if (i + 1 < KP / 32) {
            asm volatile("cp.async.wait_group 1;" ::: "memory");
        } else {
            asm volatile("cp.async.wait_group 0;" ::: "memory");
        }
        __syncthreads();
        uint32_t sA = sA0 + (uint32_t)(i % 3) * (128 * LPITCH * 2);
        uint32_t sB = sB0 + (uint32_t)(i % 3) * (128 * LPITCH * 2);
#pragma unroll
        for (int ks = 0; ks < 32; ks += 16) {
            uint32_t af[4][4], bfr[2][4];
#pragma unroll
            for (int mt = 0; mt < 4; mt++)
                ldm_x4(af[mt],
                       sA + (uint32_t)(((wm * 64 + mt * 16 + lrow) * LPITCH + ks + lcol) * 2));
#pragma unroll
            for (int np = 0; np < 2; np++)
                ldm_x4(bfr[np],
                       sB + (uint32_t)(((wn * 32 + np * 16 + lrow) * LPITCH + ks + lcol) * 2));
#pragma unroll
            for (int mt = 0; mt < 4; mt++) {
#pragma unroll
                for (int nt = 0; nt < 4; nt++) {
                    int np = nt >> 1, sub = nt & 1;
                    mma_bf16(acc[mt][nt], af[mt], bfr[np][sub], bfr[np][sub + 2]);
                }
            }
        }
        if (i + 2 < KP / 32) issue(i + 2);
    }

    int grp = lane >> 2, qc = (lane & 3) * 2;
#pragma unroll
    for (int nt = 0; nt < 4; nt++) {
        int v = v0 + wn * 32 + nt * 8 + qc;
        if (v >= VGN) continue;
        float b0 = bg[v], b1 = bg[v + 1];
#pragma unroll
        for (int mt = 0; mt < 4; mt++) {
            int t = t0 + wm * 64 + mt * 16 + grp;
            float2 o0 = make_float2(acc[mt][nt][0] + b0, acc[mt][nt][1] + b1);
            float2 o1 = make_float2(acc[mt][nt][2] + b0, acc[mt][nt][3] + b1);
            *(float2*)&out[(size_t)t * VGN + v] = o0;
            *(float2*)&out[(size_t)(t + 8) * VGN + v] = o1;
        }
    }
}

// ---------------- kernel 6: log_softmax, online max+sum (2 passes total) -----
__global__ __launch_bounds__(512) void k_logsoftmax(float* __restrict__ out) {
    int t = blockIdx.x;
    float* row = out + (size_t)t * VGN;
    __shared__ float rm[16], rs[16];
    int tid = threadIdx.x;
    int lane = tid & 31, w = tid >> 5;

    float mr = -1e30f, sr = 0.f;
    const float4* row4 = (const float4*)row;
    for (int v = tid; v < VGN / 4; v += 512) {
        float4 x = row4[v];
        float xs[4] = {x.x, x.y, x.z, x.w};
#pragma unroll
        for (int c = 0; c < 4; c++) {
            float xv = xs[c];
            if (xv <= mr) {
                sr += __expf(xv - mr);
            } else {
                sr = sr * __expf(mr - xv) + 1.f;
                mr = xv;
            }
        }
    }
#pragma unroll
    for (int o = 16; o; o >>= 1) {
        float mo = __shfl_xor_sync(~0u, mr, o);
        float so = __shfl_xor_sync(~0u, sr, o);
        float nm = fmaxf(mr, mo);
        sr = sr * __expf(mr - nm) + so * __expf(mo - nm);
        mr = nm;
    }
    if (lane == 0) { rm[w] = mr; rs[w] = sr; }
    __syncthreads();
    if (tid == 0) {
        float M = rm[0], S = rs[0];
#pragma unroll
        for (int i = 1; i < 16; i++) {
            float nm = fmaxf(M, rm[i]);
            S = S * __expf(M - nm) + rs[i] * __expf(rm[i] - nm);
            M = nm;
        }
        rm[0] = M + logf(S);
    }
    __syncthreads();
    float lse = rm[0];

    float4* row4w = (float4*)row;
    for (int v = tid; v < VGN / 4; v += 512) {
        float4 x = row4w[v];
        x.x -= lse; x.y -= lse; x.z -= lse; x.w -= lse;
        row4w[v] = x;
    }
}

// ---------------- tail zero (second ref output = zeros) ----------------
__global__ void k_zero(float* out, size_t start, size_t n) {
    size_t i = (size_t)blockIdx.x * blockDim.x + threadIdx.x;
    if (i < n) out[start + i] = 0.f;
}

extern "C" void kernel_launch(void* const* d_in, const int* in_sizes, int n_in,
                              void* d_out, int out_size) {
    const int*   xidx  = (const int*)d_in[0];
    const int*   esrc  = (const int*)d_in[1];
    const int*   edst  = (const int*)d_in[2];
    const float* X     = (const float*)d_in[3];
    const float* convW = (const float*)d_in[4];
    const float* W0    = (const float*)d_in[5];
    const float* Wu    = (const float*)d_in[6];
    const float* Uu    = (const float*)d_in[7];
    const float* Wg    = (const float*)d_in[8];
    const float* bg    = (const float*)d_in[9];
    float* out = (float*)d_out;

    k_gatherY<<<T_STEPS, 256>>>(xidx, X, esrc, edst);
    {
        size_t nw = ((size_t)VP * KP) / 2;
        k_cvtW<<<(unsigned)((nw + 255) / 256), 256>>>(Wg);
    }
    k_trWu<<<dim3(KFLAT / 32, NP / 32), 1024>>>(Wu);
    k_trWcat<<<dim3(KY / 32, NP / 32), 1024>>>(convW, W0);
    k_tcgemm<<<dim3(3, 4, UKS), 256>>>(0);   // U partials
    k_tcgemm<<<dim3(3, 4, PKS), 256>>>(1);   // P partials
    k_reduce2<<<(TD + 255) / 256, 256>>>();
    k_recur8<<<8, R8T>>>(Uu);
    k_logits_mma<<<dim3(VP / 128, T_STEPS / 128), 256>>>(bg, out);
    k_logsoftmax<<<T_STEPS, 512>>>(out);

    size_t used = (size_t)T_STEPS * VGN;
    if ((size_t)out_size > used) {
        size_t n = (size_t)out_size - used;
        k_zero<<<(unsigned)((n + 255) / 256), 256>>>(out, used, n);
    }
}